// round 14
// baseline (speedup 1.0000x reference)
#include <cuda_runtime.h>
#include <cuda_bf16.h>
#include <math.h>

#define FULLMASK 0xFFFFFFFFu

// Problem constants (fixed by the dataset)
#define NMAX   16384
#define INCH   128
#define SDIM   4
#define PDIM   64
#define OUTCH  128
#define KNN    50
#define NPER   4096   // nodes per segment (16384 / 4 splits)
#define NPAIR  (NPER/2)
#define CAP    192    // collection buffer per query
#define PREP   256    // prefix pairs (512 candidates) for threshold estimate

typedef unsigned long long u64t;

// ---------------- device scratch (no allocation allowed) ----------------
__device__ float g_space[NMAX * SDIM];
__device__ float g_prop [NMAX * PDIM];
__device__ int   g_idx  [NMAX * KNN];
__device__ float g_w    [NMAX * KNN];   // exp(-10*d2), precomputed for k3

// Bit-exact replication of reference arithmetic (do not touch):
__device__ __forceinline__ float xla_sq4(float4 c) {
    return __fadd_rn(__fadd_rn(__fadd_rn(__fmul_rn(c.x, c.x), __fmul_rn(c.y, c.y)),
                               __fmul_rn(c.z, c.z)),
                     __fmul_rn(c.w, c.w));
}
__device__ __forceinline__ float cublas_dot4(float4 a, float4 b) {
    return __fmaf_rn(a.w, b.w, __fmaf_rn(a.z, b.z, __fmaf_rn(a.y, b.y, __fmul_rn(a.x, b.x))));
}
__device__ __forceinline__ float d2f(float4 cq, float sqq, float4 cj, float sqj) {
    const float dot = cublas_dot4(cq, cj);
    const float t   = __fadd_rn(sqq, sqj);
    return fmaxf(__fadd_rn(t, __fmul_rn(-2.0f, dot)), 0.0f);
}

// ---------------- packed fp32x2 helpers (sm_103a) ----------------
__device__ __forceinline__ u64t p2_pack(float lo, float hi) {
    u64t r; asm("mov.b64 %0, {%1, %2};" : "=l"(r) : "f"(lo), "f"(hi)); return r;
}
__device__ __forceinline__ void p2_unpack(u64t v, float& lo, float& hi) {
    asm("mov.b64 {%0, %1}, %2;" : "=f"(lo), "=f"(hi) : "l"(v));
}
__device__ __forceinline__ u64t p2_mul(u64t a, u64t b) {
    u64t r; asm("mul.rn.f32x2 %0, %1, %2;" : "=l"(r) : "l"(a), "l"(b)); return r;
}
__device__ __forceinline__ u64t p2_add(u64t a, u64t b) {
    u64t r; asm("add.rn.f32x2 %0, %1, %2;" : "=l"(r) : "l"(a), "l"(b)); return r;
}
__device__ __forceinline__ u64t p2_fma(u64t a, u64t b, u64t c) {
    u64t r; asm("fma.rn.f32x2 %0, %1, %2, %3;" : "=l"(r) : "l"(a), "l"(b), "l"(c)); return r;
}
__device__ __forceinline__ u64t mk64(unsigned lo, unsigned hi) {
    u64t r; asm("mov.b64 %0, {%1, %2};" : "=l"(r) : "r"(lo), "r"(hi)); return r;
}

// per-lane two candidates, one query: same RN op sequence as d2f (per lane)
__device__ __forceinline__ u64t d2pair(u64t qx2, u64t qy2, u64t qz2, u64t qw2,
                                       u64t sqq2, uint4 A, uint4 B, u64t sj2, u64t neg2) {
    const u64t x2 = mk64(A.x, A.y), y2 = mk64(A.z, A.w);
    const u64t z2 = mk64(B.x, B.y), w2 = mk64(B.z, B.w);
    u64t dot = p2_mul(qx2, x2);
    dot = p2_fma(qy2, y2, dot);
    dot = p2_fma(qz2, z2, dot);
    dot = p2_fma(qw2, w2, dot);
    return p2_add(p2_add(sqq2, sj2), p2_mul(neg2, dot));
}

#define TOP2_UPD(a0, a1, v) do { a1 = fminf(a1, fmaxf(a0, v)); a0 = fminf(a0, v); } while (0)

// ---------------- K1: space = x@Ws + bs ; prop = x@Wp + bp ----------------
__global__ __launch_bounds__(256) void k1_project(
        const float* __restrict__ x,
        const float* __restrict__ Ws, const float* __restrict__ bs,
        const float* __restrict__ Wp, const float* __restrict__ bp,
        float* __restrict__ out, int N) {
    __shared__ __align__(16) float sx [64 * INCH];
    __shared__ __align__(16) float sWp[INCH * PDIM];
    __shared__ float sWs[INCH * SDIM];
    const int tid = threadIdx.x;
    const int base = blockIdx.x * 64;

    for (int i = tid * 4; i < 64 * INCH; i += 1024)
        *(float4*)&sx[i] = *(const float4*)&x[(size_t)base * INCH + i];
    for (int i = tid * 4; i < INCH * PDIM; i += 1024)
        *(float4*)&sWp[i] = *(const float4*)&Wp[i];
    for (int i = tid; i < INCH * SDIM; i += 256) sWs[i] = Ws[i];
    __syncthreads();

    {
        const int cg = (tid & 15) * 4;
        const int ng = (tid >> 4) * 4;
        float acc[4][4];
        #pragma unroll
        for (int i = 0; i < 4; i++) {
            const float4 b4 = *(const float4*)&bp[cg];
            acc[i][0] = b4.x; acc[i][1] = b4.y; acc[i][2] = b4.z; acc[i][3] = b4.w;
        }
        for (int kk = 0; kk < INCH; kk += 4) {
            float4 xv[4];
            #pragma unroll
            for (int i = 0; i < 4; i++) xv[i] = *(const float4*)&sx[(ng + i) * INCH + kk];
            #pragma unroll
            for (int q = 0; q < 4; q++) {
                const float4 w4 = *(const float4*)&sWp[(kk + q) * PDIM + cg];
                #pragma unroll
                for (int i = 0; i < 4; i++) {
                    const float xs = (q == 0) ? xv[i].x : (q == 1) ? xv[i].y
                                   : (q == 2) ? xv[i].z : xv[i].w;
                    acc[i][0] = __fmaf_rn(xs, w4.x, acc[i][0]);
                    acc[i][1] = __fmaf_rn(xs, w4.y, acc[i][1]);
                    acc[i][2] = __fmaf_rn(xs, w4.z, acc[i][2]);
                    acc[i][3] = __fmaf_rn(xs, w4.w, acc[i][3]);
                }
            }
        }
        #pragma unroll
        for (int i = 0; i < 4; i++) {
            float4 r; r.x = acc[i][0]; r.y = acc[i][1]; r.z = acc[i][2]; r.w = acc[i][3];
            *(float4*)&g_prop[(size_t)(base + ng + i) * PDIM + cg] = r;
        }
    }

    {
        const int node = tid >> 2, cs = tid & 3;
        const float* xr = &sx[node * INCH];
        float s[4];
        #pragma unroll
        for (int sl = 0; sl < 4; sl++) {
            float acc = 0.0f;
            const int k0 = sl * 32;
            #pragma unroll
            for (int kk = 0; kk < 32; kk++)
                acc = __fmaf_rn(xr[k0 + kk], sWs[(k0 + kk) * SDIM + cs], acc);
            s[sl] = acc;
        }
        const float g = __fadd_rn(__fadd_rn(__fadd_rn(s[0], s[1]), s[2]), s[3]);
        const float v = __fadd_rn(g, bs[cs]);
        const int gn = base + node;
        g_space[(size_t)gn * SDIM + cs] = v;
        out[(size_t)N * 228 + (size_t)gn * SDIM + cs] = v;
    }
}

// ---------------- K2 v7: speculative-prefix threshold, single full sweep ----------------
// 256 threads = 8 warps; warp owns 2 queries; 16 queries/block; grid 1024.
// smem: sA 32KB | sB 32KB | sSq2 16KB | sVal u32[16*CAP] 12KB | sIdx u16[16*CAP] 6KB
//       = 98 KB -> 2 CTAs/SM
#define K2_SMEM (NPAIR*16*2 + NPAIR*8 + 16*CAP*4 + 16*CAP*2)

__device__ __forceinline__ void k2_write(unsigned vbits, int j, int rank, int gq,
                                         int segBase, float* __restrict__ out, int N) {
    const float v = __uint_as_float(vbits);
    const int gi = segBase + j;
    g_idx[(size_t)gq * KNN + rank] = gi;
    g_w  [(size_t)gq * KNN + rank] = expf(-10.0f * v);
    out[(size_t)N * 128 + (size_t)gq * KNN + rank] = (float)gi;
    out[(size_t)N * 178 + (size_t)gq * KNN + rank] = v;
}

// rank-12 (0-based rank 11) of the 128 clamped subset values (4 per lane).
// Subset = per-lane/stream top-2 of the 512-candidate prefix. The result is
// >= the true 12th-smallest of the prefix -> a LOOSER (safe) threshold.
__device__ __forceinline__ float selectR_128(unsigned* __restrict__ bv,
                                             unsigned short* __restrict__ bi,
                                             float e0, float e1, float o0, float o1,
                                             int lane) {
    const unsigned base = lane * 4;
    const u64t k0 = ((u64t)__float_as_uint(e0) << 16) | (base + 0);
    const u64t k1 = ((u64t)__float_as_uint(e1) << 16) | (base + 1);
    const u64t k2 = ((u64t)__float_as_uint(o0) << 16) | (base + 2);
    const u64t k3 = ((u64t)__float_as_uint(o1) << 16) | (base + 3);
    bv[base + 0] = __float_as_uint(e0); bi[base + 0] = (unsigned short)(base + 0);
    bv[base + 1] = __float_as_uint(e1); bi[base + 1] = (unsigned short)(base + 1);
    bv[base + 2] = __float_as_uint(o0); bi[base + 2] = (unsigned short)(base + 2);
    bv[base + 3] = __float_as_uint(o1); bi[base + 3] = (unsigned short)(base + 3);
    __syncwarp();
    int r0 = 0, r1 = 0, r2 = 0, r3 = 0;
    #pragma unroll 8
    for (int n = 0; n < 128; n++) {
        const u64t u = ((u64t)bv[n] << 16) | bi[n];
        r0 += (u < k0); r1 += (u < k1); r2 += (u < k2); r3 += (u < k3);
    }
    const bool h = (r0 == 11) || (r1 == 11) || (r2 == 11) || (r3 == 11);
    const float vh = (r0 == 11) ? e0 : ((r1 == 11) ? e1 : ((r2 == 11) ? o0 : o1));
    const unsigned m = __ballot_sync(FULLMASK, h);
    const float res = __shfl_sync(FULLMASK, vh, __ffs(m) - 1);
    __syncwarp();
    return res;
}

__device__ void k2_finalize(const unsigned* __restrict__ bv,
                            const unsigned short* __restrict__ bi,
                            unsigned cnt, int gq,
                            float4 cq, float sqq, int segBase, int lane,
                            const float4* __restrict__ gs4,
                            float* __restrict__ out, int N) {
    if (cnt >= KNN && cnt <= CAP) {
        // cnt >= 50 hits <= T proves T >= tau_50 -> collected set is a superset
        // of the exact top-50; rank-sort is exact.
        for (int m = lane; m < (int)cnt; m += 32) {
            const u64t key = ((u64t)bv[m] << 16) | bi[m];
            int rank = 0;
            for (int n = 0; n < (int)cnt; n++) {
                const u64t u = ((u64t)bv[n] << 16) | bi[n];
                rank += (u < key);
            }
            if (rank < KNN)
                k2_write(bv[m], (int)bi[m], rank, gq, segBase, out, N);
        }
    } else {
        // Exact deterministic fallback (estimate too tight/loose; ~never taken).
        long long prev = -1;
        for (int r = 0; r < KNN; r++) {
            u64t best = ~0ull;
            for (int j = lane; j < NPER; j += 32) {
                const float4 cj = gs4[segBase + j];
                const float v = d2f(cq, sqq, cj, xla_sq4(cj));
                const u64t key = ((u64t)__float_as_uint(v) << 16) | (unsigned)j;
                if ((long long)key > prev && key < best) best = key;
            }
            #pragma unroll
            for (int off = 16; off; off >>= 1) {
                const u64t o = __shfl_xor_sync(FULLMASK, best, off);
                if (o < best) best = o;
            }
            if (lane == 0)
                k2_write((unsigned)(best >> 16), (int)(best & 0xFFFFull), r, gq, segBase, out, N);
            prev = (long long)best;
        }
    }
}

__global__ __launch_bounds__(256) void k2_knn(float* __restrict__ out, int N) {
    extern __shared__ unsigned char dsm[];
    uint4*          sA   = (uint4*)dsm;                                 // 32 KB
    uint4*          sB   = (uint4*)(dsm + NPAIR * 16);                  // 32 KB
    u64t*           sSq2 = (u64t*)(dsm + NPAIR * 32);                   // 16 KB
    unsigned*       sVal = (unsigned*)(dsm + NPAIR * 40);               // 12 KB
    unsigned short* sIdx = (unsigned short*)(dsm + NPAIR * 40 + 16 * CAP * 4); // 6 KB
    __shared__ unsigned scnt[16];

    const int tid = threadIdx.x;
    const int w = tid >> 5, lane = tid & 31;
    const int qBase = blockIdx.x * 16;
    const int segBase = qBase & ~(NPER - 1);
    const float4* gs4 = (const float4*)g_space;

    for (int p = tid; p < NPAIR; p += 256) {
        const float4 c0 = gs4[segBase + 2 * p];
        const float4 c1 = gs4[segBase + 2 * p + 1];
        sA[p] = make_uint4(__float_as_uint(c0.x), __float_as_uint(c1.x),
                           __float_as_uint(c0.y), __float_as_uint(c1.y));
        sB[p] = make_uint4(__float_as_uint(c0.z), __float_as_uint(c1.z),
                           __float_as_uint(c0.w), __float_as_uint(c1.w));
        sSq2[p] = p2_pack(xla_sq4(c0), xla_sq4(c1));
    }
    if (tid < 16) scnt[tid] = 0;
    __syncthreads();

    const int q0 = qBase + 2 * w, q1 = q0 + 1;
    const float4 cq0 = gs4[q0]; const float sqq0 = xla_sq4(cq0);
    const float4 cq1 = gs4[q1]; const float sqq1 = xla_sq4(cq1);
    const u64t q0x = p2_pack(cq0.x, cq0.x), q0y = p2_pack(cq0.y, cq0.y),
               q0z = p2_pack(cq0.z, cq0.z), q0w = p2_pack(cq0.w, cq0.w);
    const u64t q1x = p2_pack(cq1.x, cq1.x), q1y = p2_pack(cq1.y, cq1.y),
               q1z = p2_pack(cq1.z, cq1.z), q1w = p2_pack(cq1.w, cq1.w);
    const u64t sqq0p = p2_pack(sqq0, sqq0), sqq1p = p2_pack(sqq1, sqq1);
    const u64t neg2  = p2_pack(-2.0f, -2.0f);
    unsigned*       bv0 = sVal + (size_t)(2 * w) * CAP;
    unsigned*       bv1 = bv0 + CAP;
    unsigned short* bi0 = sIdx + (size_t)(2 * w) * CAP;
    unsigned short* bi1 = bi0 + CAP;

    // ---- Phase A: prefix sweep (512 candidates), per-lane/stream top-2 ----
    float aE0 = INFINITY, aE1 = INFINITY, aO0 = INFINITY, aO1 = INFINITY;
    float bE0 = INFINITY, bE1 = INFINITY, bO0 = INFINITY, bO1 = INFINITY;
    for (int p = lane; p < PREP; p += 32) {
        const uint4 A = sA[p]; const uint4 B = sB[p]; const u64t sj2 = sSq2[p];
        {
            const u64t r2 = d2pair(q0x, q0y, q0z, q0w, sqq0p, A, B, sj2, neg2);
            float vE, vO; p2_unpack(r2, vE, vO);
            TOP2_UPD(aE0, aE1, vE);
            TOP2_UPD(aO0, aO1, vO);
        }
        {
            const u64t r2 = d2pair(q1x, q1y, q1z, q1w, sqq1p, A, B, sj2, neg2);
            float vE, vO; p2_unpack(r2, vE, vO);
            TOP2_UPD(bE0, bE1, vE);
            TOP2_UPD(bO0, bO1, vO);
        }
    }

    // ---- Speculative thresholds: rank-12 of the 128-value prefix subset ----
    const float T0 = selectR_128(bv0, bi0, fmaxf(aE0, 0.0f), fmaxf(aE1, 0.0f),
                                           fmaxf(aO0, 0.0f), fmaxf(aO1, 0.0f), lane);
    const float T1 = selectR_128(bv1, bi1, fmaxf(bE0, 0.0f), fmaxf(bE1, 0.0f),
                                           fmaxf(bO0, 0.0f), fmaxf(bO1, 0.0f), lane);

    // ---- Single full sweep: collect all d2 <= T ----
    unsigned* cnt0 = &scnt[2 * w];
    unsigned* cnt1 = &scnt[2 * w + 1];
    for (int p = lane; p < NPAIR; p += 32) {
        const uint4 A = sA[p]; const uint4 B = sB[p]; const u64t sj2 = sSq2[p];
        {
            const u64t r2 = d2pair(q0x, q0y, q0z, q0w, sqq0p, A, B, sj2, neg2);
            float vE, vO; p2_unpack(r2, vE, vO);
            if (vE <= T0) {
                const unsigned pos = atomicAdd(cnt0, 1u);
                if (pos < CAP) {
                    bv0[pos] = __float_as_uint(fmaxf(vE, 0.0f));
                    bi0[pos] = (unsigned short)(2 * p);
                }
            }
            if (vO <= T0) {
                const unsigned pos = atomicAdd(cnt0, 1u);
                if (pos < CAP) {
                    bv0[pos] = __float_as_uint(fmaxf(vO, 0.0f));
                    bi0[pos] = (unsigned short)(2 * p + 1);
                }
            }
        }
        {
            const u64t r2 = d2pair(q1x, q1y, q1z, q1w, sqq1p, A, B, sj2, neg2);
            float vE, vO; p2_unpack(r2, vE, vO);
            if (vE <= T1) {
                const unsigned pos = atomicAdd(cnt1, 1u);
                if (pos < CAP) {
                    bv1[pos] = __float_as_uint(fmaxf(vE, 0.0f));
                    bi1[pos] = (unsigned short)(2 * p);
                }
            }
            if (vO <= T1) {
                const unsigned pos = atomicAdd(cnt1, 1u);
                if (pos < CAP) {
                    bv1[pos] = __float_as_uint(fmaxf(vO, 0.0f));
                    bi1[pos] = (unsigned short)(2 * p + 1);
                }
            }
        }
    }
    __syncwarp();

    // ---- Final exact rank-sort + writes (count check proves exactness) ----
    k2_finalize(bv0, bi0, *cnt0, q0, cq0, sqq0, segBase, lane, gs4, out, N);
    k2_finalize(bv1, bi1, *cnt1, q1, cq1, sqq1, segBase, lane, gs4, out, N);
}

// ---------------- K3 v3: interleaved float4 gather + output GEMM + relu ----------------
__global__ __launch_bounds__(256) void k3_aggregate(
        const float* __restrict__ x,
        const float* __restrict__ Wo, const float* __restrict__ bo,
        float* __restrict__ out) {
    __shared__ __align__(16) float feat[32][2 * PDIM + INCH];   // 32 KB
    __shared__ float swarr[32 * KNN];
    __shared__ int   sgidx[32 * KNN];

    const int tid = threadIdx.x;
    const int base = blockIdx.x * 32;

    for (int i = tid * 4; i < 32 * INCH; i += 1024) {
        const int node = i >> 7, c = i & 127;
        *(float4*)&feat[node][c] = *(const float4*)&x[(size_t)(base + node) * INCH + c];
    }
    for (int i = tid; i < 32 * KNN; i += 256) {
        swarr[i] = g_w  [(size_t)base * KNN + i];
        sgidx[i] = g_idx[(size_t)base * KNN + i];
    }
    __syncthreads();

    // Gather: both node-passes interleaved (2 independent LDG chains / iter).
    {
        const int nnA = tid >> 4;          // 0..15
        const int nnB = nnA + 16;          // 16..31
        const int c4  = (tid & 15) * 4;
        const int*   irA = &sgidx[nnA * KNN]; const float* wrA = &swarr[nnA * KNN];
        const int*   irB = &sgidx[nnB * KNN]; const float* wrB = &swarr[nnB * KNN];
        float axA = 0.0f, ayA = 0.0f, azA = 0.0f, awA = 0.0f;
        float mxA = -INFINITY, myA = -INFINITY, mzA = -INFINITY, mwA = -INFINITY;
        float axB = 0.0f, ayB = 0.0f, azB = 0.0f, awB = 0.0f;
        float mxB = -INFINITY, myB = -INFINITY, mzB = -INFINITY, mwB = -INFINITY;
        #pragma unroll 5
        for (int r = 0; r < KNN; r++) {
            const float4 pA = *(const float4*)&g_prop[(size_t)irA[r] * PDIM + c4];
            const float4 pB = *(const float4*)&g_prop[(size_t)irB[r] * PDIM + c4];
            const float wA = wrA[r], wB = wrB[r];
            const float vxA = pA.x * wA, vyA = pA.y * wA, vzA = pA.z * wA, vwA = pA.w * wA;
            const float vxB = pB.x * wB, vyB = pB.y * wB, vzB = pB.z * wB, vwB = pB.w * wB;
            axA += vxA; ayA += vyA; azA += vzA; awA += vwA;
            mxA = fmaxf(mxA, vxA); myA = fmaxf(myA, vyA);
            mzA = fmaxf(mzA, vzA); mwA = fmaxf(mwA, vwA);
            axB += vxB; ayB += vyB; azB += vzB; awB += vwB;
            mxB = fmaxf(mxB, vxB); myB = fmaxf(myB, vyB);
            mzB = fmaxf(mzB, vzB); mwB = fmaxf(mwB, vwB);
        }
        const float s = 1.0f / (float)KNN;
        float4 fmA; fmA.x = axA * s; fmA.y = ayA * s; fmA.z = azA * s; fmA.w = awA * s;
        float4 fxA; fxA.x = mxA; fxA.y = myA; fxA.z = mzA; fxA.w = mwA;
        float4 fmB; fmB.x = axB * s; fmB.y = ayB * s; fmB.z = azB * s; fmB.w = awB * s;
        float4 fxB; fxB.x = mxB; fxB.y = myB; fxB.z = mzB; fxB.w = mwB;
        *(float4*)&feat[nnA][INCH + c4]        = fmA;
        *(float4*)&feat[nnA][INCH + PDIM + c4] = fxA;
        *(float4*)&feat[nnB][INCH + c4]        = fmB;
        *(float4*)&feat[nnB][INCH + PDIM + c4] = fxB;
    }
    __syncthreads();

    const int c = tid & 127;
    const int t0 = (tid >> 7) * 16;
    float acc[16];
    #pragma unroll
    for (int t = 0; t < 16; t++) acc[t] = bo[c];
    for (int kk = 0; kk < 2 * PDIM + INCH; kk += 4) {
        const float w0 = Wo[(size_t)(kk + 0) * OUTCH + c];
        const float w1 = Wo[(size_t)(kk + 1) * OUTCH + c];
        const float w2 = Wo[(size_t)(kk + 2) * OUTCH + c];
        const float w3 = Wo[(size_t)(kk + 3) * OUTCH + c];
        #pragma unroll
        for (int t = 0; t < 16; t++) {
            const float4 f = *(const float4*)&feat[t0 + t][kk];
            acc[t] = __fmaf_rn(f.x, w0, acc[t]);
            acc[t] = __fmaf_rn(f.y, w1, acc[t]);
            acc[t] = __fmaf_rn(f.z, w2, acc[t]);
            acc[t] = __fmaf_rn(f.w, w3, acc[t]);
        }
    }
    #pragma unroll
    for (int t = 0; t < 16; t++)
        out[(size_t)(base + t0 + t) * OUTCH + c] = fmaxf(acc[t], 0.0f);
}

// ---------------- launch ----------------
extern "C" void kernel_launch(void* const* d_in, const int* in_sizes, int n_in,
                              void* d_out, int out_size) {
    const float* x  = (const float*)d_in[0];
    const float* Ws = (const float*)d_in[2];
    const float* bs = (const float*)d_in[3];
    const float* Wp = (const float*)d_in[4];
    const float* bp = (const float*)d_in[5];
    const float* Wo = (const float*)d_in[6];
    const float* bo = (const float*)d_in[7];

    const int N = in_sizes[0] / INCH;   // 16384
    float* out = (float*)d_out;

    k1_project<<<N / 64, 256>>>(x, Ws, bs, Wp, bp, out, N);

    cudaFuncSetAttribute(k2_knn, cudaFuncAttributeMaxDynamicSharedMemorySize, K2_SMEM);
    k2_knn<<<N / 16, 256, K2_SMEM>>>(out, N);

    k3_aggregate<<<N / 32, 256>>>(x, Wo, bo, out);

    (void)n_in; (void)in_sizes; (void)out_size;
}

// round 15
// speedup vs baseline: 5.2928x; 5.2928x over previous
#include <cuda_runtime.h>
#include <cuda_bf16.h>
#include <math.h>

#define FULLMASK 0xFFFFFFFFu

// Problem constants (fixed by the dataset)
#define NMAX   16384
#define INCH   128
#define SDIM   4
#define PDIM   64
#define OUTCH  128
#define KNN    50
#define NPER   4096   // nodes per segment (16384 / 4 splits)
#define NPAIR  (NPER/2)
#define CAP    128    // collection buffer per query

typedef unsigned long long u64t;

// ---------------- device scratch (no allocation allowed) ----------------
__device__ float g_space[NMAX * SDIM];
__device__ float g_prop [NMAX * PDIM];
__device__ int   g_idx  [NMAX * KNN];
__device__ float g_w    [NMAX * KNN];   // exp(-10*d2), precomputed for k3

// Bit-exact replication of reference arithmetic (do not touch):
__device__ __forceinline__ float xla_sq4(float4 c) {
    return __fadd_rn(__fadd_rn(__fadd_rn(__fmul_rn(c.x, c.x), __fmul_rn(c.y, c.y)),
                               __fmul_rn(c.z, c.z)),
                     __fmul_rn(c.w, c.w));
}
__device__ __forceinline__ float cublas_dot4(float4 a, float4 b) {
    return __fmaf_rn(a.w, b.w, __fmaf_rn(a.z, b.z, __fmaf_rn(a.y, b.y, __fmul_rn(a.x, b.x))));
}
__device__ __forceinline__ float d2f(float4 cq, float sqq, float4 cj, float sqj) {
    const float dot = cublas_dot4(cq, cj);
    const float t   = __fadd_rn(sqq, sqj);
    return fmaxf(__fadd_rn(t, __fmul_rn(-2.0f, dot)), 0.0f);
}

// ---------------- packed fp32x2 helpers (sm_103a) ----------------
__device__ __forceinline__ u64t p2_pack(float lo, float hi) {
    u64t r; asm("mov.b64 %0, {%1, %2};" : "=l"(r) : "f"(lo), "f"(hi)); return r;
}
__device__ __forceinline__ void p2_unpack(u64t v, float& lo, float& hi) {
    asm("mov.b64 {%0, %1}, %2;" : "=f"(lo), "=f"(hi) : "l"(v));
}
__device__ __forceinline__ u64t p2_mul(u64t a, u64t b) {
    u64t r; asm("mul.rn.f32x2 %0, %1, %2;" : "=l"(r) : "l"(a), "l"(b)); return r;
}
__device__ __forceinline__ u64t p2_add(u64t a, u64t b) {
    u64t r; asm("add.rn.f32x2 %0, %1, %2;" : "=l"(r) : "l"(a), "l"(b)); return r;
}
__device__ __forceinline__ u64t p2_fma(u64t a, u64t b, u64t c) {
    u64t r; asm("fma.rn.f32x2 %0, %1, %2, %3;" : "=l"(r) : "l"(a), "l"(b), "l"(c)); return r;
}
__device__ __forceinline__ u64t mk64(unsigned lo, unsigned hi) {
    u64t r; asm("mov.b64 %0, {%1, %2};" : "=l"(r) : "r"(lo), "r"(hi)); return r;
}

// per-lane two candidates, one query: same RN op sequence as d2f (per lane)
__device__ __forceinline__ u64t d2pair(u64t qx2, u64t qy2, u64t qz2, u64t qw2,
                                       u64t sqq2, uint4 A, uint4 B, u64t sj2, u64t neg2) {
    const u64t x2 = mk64(A.x, A.y), y2 = mk64(A.z, A.w);
    const u64t z2 = mk64(B.x, B.y), w2 = mk64(B.z, B.w);
    u64t dot = p2_mul(qx2, x2);
    dot = p2_fma(qy2, y2, dot);
    dot = p2_fma(qz2, z2, dot);
    dot = p2_fma(qw2, w2, dot);
    return p2_add(p2_add(sqq2, sj2), p2_mul(neg2, dot));
}

#define TOP2_UPD(a0, a1, v) do { a1 = fminf(a1, fmaxf(a0, v)); a0 = fminf(a0, v); } while (0)

// ---------------- K1: space = x@Ws + bs ; prop = x@Wp + bp ----------------
__global__ __launch_bounds__(256) void k1_project(
        const float* __restrict__ x,
        const float* __restrict__ Ws, const float* __restrict__ bs,
        const float* __restrict__ Wp, const float* __restrict__ bp,
        float* __restrict__ out, int N) {
    __shared__ __align__(16) float sx [64 * INCH];
    __shared__ __align__(16) float sWp[INCH * PDIM];
    __shared__ float sWs[INCH * SDIM];
    const int tid = threadIdx.x;
    const int base = blockIdx.x * 64;

    for (int i = tid * 4; i < 64 * INCH; i += 1024)
        *(float4*)&sx[i] = *(const float4*)&x[(size_t)base * INCH + i];
    for (int i = tid * 4; i < INCH * PDIM; i += 1024)
        *(float4*)&sWp[i] = *(const float4*)&Wp[i];
    for (int i = tid; i < INCH * SDIM; i += 256) sWs[i] = Ws[i];
    __syncthreads();

    {
        const int cg = (tid & 15) * 4;
        const int ng = (tid >> 4) * 4;
        float acc[4][4];
        #pragma unroll
        for (int i = 0; i < 4; i++) {
            const float4 b4 = *(const float4*)&bp[cg];
            acc[i][0] = b4.x; acc[i][1] = b4.y; acc[i][2] = b4.z; acc[i][3] = b4.w;
        }
        for (int kk = 0; kk < INCH; kk += 4) {
            float4 xv[4];
            #pragma unroll
            for (int i = 0; i < 4; i++) xv[i] = *(const float4*)&sx[(ng + i) * INCH + kk];
            #pragma unroll
            for (int q = 0; q < 4; q++) {
                const float4 w4 = *(const float4*)&sWp[(kk + q) * PDIM + cg];
                #pragma unroll
                for (int i = 0; i < 4; i++) {
                    const float xs = (q == 0) ? xv[i].x : (q == 1) ? xv[i].y
                                   : (q == 2) ? xv[i].z : xv[i].w;
                    acc[i][0] = __fmaf_rn(xs, w4.x, acc[i][0]);
                    acc[i][1] = __fmaf_rn(xs, w4.y, acc[i][1]);
                    acc[i][2] = __fmaf_rn(xs, w4.z, acc[i][2]);
                    acc[i][3] = __fmaf_rn(xs, w4.w, acc[i][3]);
                }
            }
        }
        #pragma unroll
        for (int i = 0; i < 4; i++) {
            float4 r; r.x = acc[i][0]; r.y = acc[i][1]; r.z = acc[i][2]; r.w = acc[i][3];
            *(float4*)&g_prop[(size_t)(base + ng + i) * PDIM + cg] = r;
        }
    }

    {
        const int node = tid >> 2, cs = tid & 3;
        const float* xr = &sx[node * INCH];
        float s[4];
        #pragma unroll
        for (int sl = 0; sl < 4; sl++) {
            float acc = 0.0f;
            const int k0 = sl * 32;
            #pragma unroll
            for (int kk = 0; kk < 32; kk++)
                acc = __fmaf_rn(xr[k0 + kk], sWs[(k0 + kk) * SDIM + cs], acc);
            s[sl] = acc;
        }
        const float g = __fadd_rn(__fadd_rn(__fadd_rn(s[0], s[1]), s[2]), s[3]);
        const float v = __fadd_rn(g, bs[cs]);
        const int gn = base + node;
        g_space[(size_t)gn * SDIM + cs] = v;
        out[(size_t)N * 228 + (size_t)gn * SDIM + cs] = v;
    }
}

// ---------------- K2 v5 (R12, measured best): f32x2 packed sweeps ----------------
// 256 threads = 8 warps; warp owns 2 queries; 16 queries/block; grid 1024.
// smem: sA 32KB | sB 32KB | sSq2 16KB | sBuf u64[16][CAP] 16KB = 96 KB, 2 CTAs/SM
#define K2_SMEM (NPAIR*16*2 + NPAIR*8 + 16*CAP*8)

__device__ __forceinline__ void k2_write(unsigned vbits, int j, int rank, int gq,
                                         int segBase, float* __restrict__ out, int N) {
    const float v = __uint_as_float(vbits);
    const int gi = segBase + j;
    g_idx[(size_t)gq * KNN + rank] = gi;
    g_w  [(size_t)gq * KNN + rank] = expf(-10.0f * v);
    out[(size_t)N * 128 + (size_t)gq * KNN + rank] = (float)gi;
    out[(size_t)N * 178 + (size_t)gq * KNN + rank] = v;
}

// rank-49 of the 128 clamped subset values (4 per lane) — tight upper bound of tau_50
__device__ __forceinline__ float select49_128(u64t* __restrict__ buf,
                                              float e0, float e1, float o0, float o1,
                                              int lane) {
    const unsigned base = lane * 4;
    const u64t k0 = ((u64t)__float_as_uint(e0) << 16) | (base + 0);
    const u64t k1 = ((u64t)__float_as_uint(e1) << 16) | (base + 1);
    const u64t k2 = ((u64t)__float_as_uint(o0) << 16) | (base + 2);
    const u64t k3 = ((u64t)__float_as_uint(o1) << 16) | (base + 3);
    buf[base + 0] = k0; buf[base + 1] = k1; buf[base + 2] = k2; buf[base + 3] = k3;
    __syncwarp();
    int r0 = 0, r1 = 0, r2 = 0, r3 = 0;
    #pragma unroll 8
    for (int n = 0; n < 128; n++) {
        const u64t u = buf[n];
        r0 += (u < k0); r1 += (u < k1); r2 += (u < k2); r3 += (u < k3);
    }
    const bool h = (r0 == 49) || (r1 == 49) || (r2 == 49) || (r3 == 49);
    const float vh = (r0 == 49) ? e0 : ((r1 == 49) ? e1 : ((r2 == 49) ? o0 : o1));
    const unsigned m = __ballot_sync(FULLMASK, h);
    const float res = __shfl_sync(FULLMASK, vh, __ffs(m) - 1);
    __syncwarp();
    return res;
}

__device__ void k2_finalize(const u64t* __restrict__ buf, unsigned cnt, int gq,
                            float4 cq, float sqq, int segBase, int lane,
                            const float4* __restrict__ gs4,
                            float* __restrict__ out, int N) {
    if (cnt >= KNN && cnt <= CAP) {
        for (int m = lane; m < (int)cnt; m += 32) {
            const u64t key = buf[m];
            int rank = 0;
            for (int n = 0; n < (int)cnt; n++) rank += (buf[n] < key);
            if (rank < KNN)
                k2_write((unsigned)(key >> 16), (int)(key & 0xFFFFull), rank, gq, segBase, out, N);
        }
    } else {
        // Exact deterministic fallback (tight threshold -> ~never taken).
        long long prev = -1;
        for (int r = 0; r < KNN; r++) {
            u64t best = ~0ull;
            for (int j = lane; j < NPER; j += 32) {
                const float4 cj = gs4[segBase + j];
                const float v = d2f(cq, sqq, cj, xla_sq4(cj));
                const u64t key = ((u64t)__float_as_uint(v) << 16) | (unsigned)j;
                if ((long long)key > prev && key < best) best = key;
            }
            #pragma unroll
            for (int off = 16; off; off >>= 1) {
                const u64t o = __shfl_xor_sync(FULLMASK, best, off);
                if (o < best) best = o;
            }
            if (lane == 0)
                k2_write((unsigned)(best >> 16), (int)(best & 0xFFFFull), r, gq, segBase, out, N);
            prev = (long long)best;
        }
    }
}

__global__ __launch_bounds__(256) void k2_knn(float* __restrict__ out, int N) {
    extern __shared__ unsigned char dsm[];
    uint4* sA   = (uint4*)dsm;                                   // 32 KB (x,y pairs)
    uint4* sB   = (uint4*)(dsm + NPAIR * 16);                    // 32 KB (z,w pairs)
    u64t*  sSq2 = (u64t*)(dsm + NPAIR * 32);                     // 16 KB
    u64t*  sBuf = (u64t*)(dsm + NPAIR * 32 + NPAIR * 8);         // 16 KB
    __shared__ unsigned scnt[16];

    const int tid = threadIdx.x;
    const int w = tid >> 5, lane = tid & 31;
    const int qBase = blockIdx.x * 16;
    const int segBase = qBase & ~(NPER - 1);
    const float4* gs4 = (const float4*)g_space;

    for (int p = tid; p < NPAIR; p += 256) {
        const float4 c0 = gs4[segBase + 2 * p];
        const float4 c1 = gs4[segBase + 2 * p + 1];
        sA[p] = make_uint4(__float_as_uint(c0.x), __float_as_uint(c1.x),
                           __float_as_uint(c0.y), __float_as_uint(c1.y));
        sB[p] = make_uint4(__float_as_uint(c0.z), __float_as_uint(c1.z),
                           __float_as_uint(c0.w), __float_as_uint(c1.w));
        sSq2[p] = p2_pack(xla_sq4(c0), xla_sq4(c1));
    }
    if (tid < 16) scnt[tid] = 0;
    __syncthreads();

    const int q0 = qBase + 2 * w, q1 = q0 + 1;
    const float4 cq0 = gs4[q0]; const float sqq0 = xla_sq4(cq0);
    const float4 cq1 = gs4[q1]; const float sqq1 = xla_sq4(cq1);
    const u64t q0x = p2_pack(cq0.x, cq0.x), q0y = p2_pack(cq0.y, cq0.y),
               q0z = p2_pack(cq0.z, cq0.z), q0w = p2_pack(cq0.w, cq0.w);
    const u64t q1x = p2_pack(cq1.x, cq1.x), q1y = p2_pack(cq1.y, cq1.y),
               q1z = p2_pack(cq1.z, cq1.z), q1w = p2_pack(cq1.w, cq1.w);
    const u64t sqq0p = p2_pack(sqq0, sqq0), sqq1p = p2_pack(sqq1, sqq1);
    const u64t neg2  = p2_pack(-2.0f, -2.0f);
    u64t* buf0 = sBuf + (size_t)(2 * w) * CAP;
    u64t* buf1 = buf0 + CAP;

    // ---- Pass 1: per-lane per-stream (even/odd) top-2 over ALL candidates ----
    float aE0 = INFINITY, aE1 = INFINITY, aO0 = INFINITY, aO1 = INFINITY;
    float bE0 = INFINITY, bE1 = INFINITY, bO0 = INFINITY, bO1 = INFINITY;
    for (int p = lane; p < NPAIR; p += 32) {
        const uint4 A = sA[p]; const uint4 B = sB[p]; const u64t sj2 = sSq2[p];
        {
            const u64t r2 = d2pair(q0x, q0y, q0z, q0w, sqq0p, A, B, sj2, neg2);
            float vE, vO; p2_unpack(r2, vE, vO);
            TOP2_UPD(aE0, aE1, vE);
            TOP2_UPD(aO0, aO1, vO);
        }
        {
            const u64t r2 = d2pair(q1x, q1y, q1z, q1w, sqq1p, A, B, sj2, neg2);
            float vE, vO; p2_unpack(r2, vE, vO);
            TOP2_UPD(bE0, bE1, vE);
            TOP2_UPD(bO0, bO1, vO);
        }
    }

    // ---- Thresholds: rank-49 of 128-subset (clamped before bit-keying) ----
    const float T0 = select49_128(buf0, fmaxf(aE0, 0.0f), fmaxf(aE1, 0.0f),
                                         fmaxf(aO0, 0.0f), fmaxf(aO1, 0.0f), lane);
    const float T1 = select49_128(buf1, fmaxf(bE0, 0.0f), fmaxf(bE1, 0.0f),
                                         fmaxf(bO0, 0.0f), fmaxf(bO1, 0.0f), lane);

    // ---- Pass 2: recompute raw pairs, collect clamped hits ----
    unsigned* cnt0 = &scnt[2 * w];
    unsigned* cnt1 = &scnt[2 * w + 1];
    for (int p = lane; p < NPAIR; p += 32) {
        const uint4 A = sA[p]; const uint4 B = sB[p]; const u64t sj2 = sSq2[p];
        {
            const u64t r2 = d2pair(q0x, q0y, q0z, q0w, sqq0p, A, B, sj2, neg2);
            float vE, vO; p2_unpack(r2, vE, vO);
            if (vE <= T0) {
                const unsigned pos = atomicAdd(cnt0, 1u);
                if (pos < CAP)
                    buf0[pos] = ((u64t)__float_as_uint(fmaxf(vE, 0.0f)) << 16) | (unsigned)(2 * p);
            }
            if (vO <= T0) {
                const unsigned pos = atomicAdd(cnt0, 1u);
                if (pos < CAP)
                    buf0[pos] = ((u64t)__float_as_uint(fmaxf(vO, 0.0f)) << 16) | (unsigned)(2 * p + 1);
            }
        }
        {
            const u64t r2 = d2pair(q1x, q1y, q1z, q1w, sqq1p, A, B, sj2, neg2);
            float vE, vO; p2_unpack(r2, vE, vO);
            if (vE <= T1) {
                const unsigned pos = atomicAdd(cnt1, 1u);
                if (pos < CAP)
                    buf1[pos] = ((u64t)__float_as_uint(fmaxf(vE, 0.0f)) << 16) | (unsigned)(2 * p);
            }
            if (vO <= T1) {
                const unsigned pos = atomicAdd(cnt1, 1u);
                if (pos < CAP)
                    buf1[pos] = ((u64t)__float_as_uint(fmaxf(vO, 0.0f)) << 16) | (unsigned)(2 * p + 1);
            }
        }
    }
    __syncwarp();

    k2_finalize(buf0, *cnt0, q0, cq0, sqq0, segBase, lane, gs4, out, N);
    k2_finalize(buf1, *cnt1, q1, cq1, sqq1, segBase, lane, gs4, out, N);
}

// ---------------- K3 v3: interleaved float4 gather + output GEMM + relu ----------------
__global__ __launch_bounds__(256) void k3_aggregate(
        const float* __restrict__ x,
        const float* __restrict__ Wo, const float* __restrict__ bo,
        float* __restrict__ out) {
    __shared__ __align__(16) float feat[32][2 * PDIM + INCH];   // 32 KB
    __shared__ float swarr[32 * KNN];
    __shared__ int   sgidx[32 * KNN];

    const int tid = threadIdx.x;
    const int base = blockIdx.x * 32;

    for (int i = tid * 4; i < 32 * INCH; i += 1024) {
        const int node = i >> 7, c = i & 127;
        *(float4*)&feat[node][c] = *(const float4*)&x[(size_t)(base + node) * INCH + c];
    }
    for (int i = tid; i < 32 * KNN; i += 256) {
        swarr[i] = g_w  [(size_t)base * KNN + i];
        sgidx[i] = g_idx[(size_t)base * KNN + i];
    }
    __syncthreads();

    // Gather: both node-passes interleaved (2 independent LDG chains / iter).
    {
        const int nnA = tid >> 4;          // 0..15
        const int nnB = nnA + 16;          // 16..31
        const int c4  = (tid & 15) * 4;
        const int*   irA = &sgidx[nnA * KNN]; const float* wrA = &swarr[nnA * KNN];
        const int*   irB = &sgidx[nnB * KNN]; const float* wrB = &swarr[nnB * KNN];
        float axA = 0.0f, ayA = 0.0f, azA = 0.0f, awA = 0.0f;
        float mxA = -INFINITY, myA = -INFINITY, mzA = -INFINITY, mwA = -INFINITY;
        float axB = 0.0f, ayB = 0.0f, azB = 0.0f, awB = 0.0f;
        float mxB = -INFINITY, myB = -INFINITY, mzB = -INFINITY, mwB = -INFINITY;
        #pragma unroll 5
        for (int r = 0; r < KNN; r++) {
            const float4 pA = *(const float4*)&g_prop[(size_t)irA[r] * PDIM + c4];
            const float4 pB = *(const float4*)&g_prop[(size_t)irB[r] * PDIM + c4];
            const float wA = wrA[r], wB = wrB[r];
            const float vxA = pA.x * wA, vyA = pA.y * wA, vzA = pA.z * wA, vwA = pA.w * wA;
            const float vxB = pB.x * wB, vyB = pB.y * wB, vzB = pB.z * wB, vwB = pB.w * wB;
            axA += vxA; ayA += vyA; azA += vzA; awA += vwA;
            mxA = fmaxf(mxA, vxA); myA = fmaxf(myA, vyA);
            mzA = fmaxf(mzA, vzA); mwA = fmaxf(mwA, vwA);
            axB += vxB; ayB += vyB; azB += vzB; awB += vwB;
            mxB = fmaxf(mxB, vxB); myB = fmaxf(myB, vyB);
            mzB = fmaxf(mzB, vzB); mwB = fmaxf(mwB, vwB);
        }
        const float s = 1.0f / (float)KNN;
        float4 fmA; fmA.x = axA * s; fmA.y = ayA * s; fmA.z = azA * s; fmA.w = awA * s;
        float4 fxA; fxA.x = mxA; fxA.y = myA; fxA.z = mzA; fxA.w = mwA;
        float4 fmB; fmB.x = axB * s; fmB.y = ayB * s; fmB.z = azB * s; fmB.w = awB * s;
        float4 fxB; fxB.x = mxB; fxB.y = myB; fxB.z = mzB; fxB.w = mwB;
        *(float4*)&feat[nnA][INCH + c4]        = fmA;
        *(float4*)&feat[nnA][INCH + PDIM + c4] = fxA;
        *(float4*)&feat[nnB][INCH + c4]        = fmB;
        *(float4*)&feat[nnB][INCH + PDIM + c4] = fxB;
    }
    __syncthreads();

    const int c = tid & 127;
    const int t0 = (tid >> 7) * 16;
    float acc[16];
    #pragma unroll
    for (int t = 0; t < 16; t++) acc[t] = bo[c];
    for (int kk = 0; kk < 2 * PDIM + INCH; kk += 4) {
        const float w0 = Wo[(size_t)(kk + 0) * OUTCH + c];
        const float w1 = Wo[(size_t)(kk + 1) * OUTCH + c];
        const float w2 = Wo[(size_t)(kk + 2) * OUTCH + c];
        const float w3 = Wo[(size_t)(kk + 3) * OUTCH + c];
        #pragma unroll
        for (int t = 0; t < 16; t++) {
            const float4 f = *(const float4*)&feat[t0 + t][kk];
            acc[t] = __fmaf_rn(f.x, w0, acc[t]);
            acc[t] = __fmaf_rn(f.y, w1, acc[t]);
            acc[t] = __fmaf_rn(f.z, w2, acc[t]);
            acc[t] = __fmaf_rn(f.w, w3, acc[t]);
        }
    }
    #pragma unroll
    for (int t = 0; t < 16; t++)
        out[(size_t)(base + t0 + t) * OUTCH + c] = fmaxf(acc[t], 0.0f);
}

// ---------------- launch ----------------
extern "C" void kernel_launch(void* const* d_in, const int* in_sizes, int n_in,
                              void* d_out, int out_size) {
    const float* x  = (const float*)d_in[0];
    const float* Ws = (const float*)d_in[2];
    const float* bs = (const float*)d_in[3];
    const float* Wp = (const float*)d_in[4];
    const float* bp = (const float*)d_in[5];
    const float* Wo = (const float*)d_in[6];
    const float* bo = (const float*)d_in[7];

    const int N = in_sizes[0] / INCH;   // 16384
    float* out = (float*)d_out;

    k1_project<<<N / 64, 256>>>(x, Ws, bs, Wp, bp, out, N);

    cudaFuncSetAttribute(k2_knn, cudaFuncAttributeMaxDynamicSharedMemorySize, K2_SMEM);
    k2_knn<<<N / 16, 256, K2_SMEM>>>(out, N);

    k3_aggregate<<<N / 32, 256>>>(x, Wo, bo, out);

    (void)n_in; (void)in_sizes; (void)out_size;
}